// round 1
// baseline (speedup 1.0000x reference)
#include <cuda_runtime.h>
#include <cuda_bf16.h>

// ZINB decoder over 3M edges.
// 8 threads per edge; each thread handles 8 of the 64 feature dims.
//   h[e,k] = c_feat[u,k] * g_feat[v,k]
//   mu_   = sigmoid(h . W_mean + b_mean)
//   disp_ =          h . W_disp + b_disp
//   pi    = sigmoid(h . W_pi   + b_pi)
//   disp  = clamp(softplus(gs * disp_), 1e-4, 1e4)
//   mu    = cs * clamp(exp(gs * mu_) - 1, 1e-5, 1e6)
// Output layout: out[0:E]=mu, out[E:2E]=disp, out[2E:3E]=pi

#define THREADS_PER_EDGE 8
#define BLOCK 256

__device__ __forceinline__ float sigmoidf_(float x) {
    return 1.0f / (1.0f + expf(-x));
}

__global__ __launch_bounds__(BLOCK)
void zinb_decoder_kernel(const float* __restrict__ c_feat,
                         const float* __restrict__ g_feat,
                         const float* __restrict__ cs_factor,
                         const float* __restrict__ gs_factor,
                         const int*   __restrict__ edge_u,
                         const int*   __restrict__ edge_v,
                         const float* __restrict__ W_mean,
                         const float* __restrict__ b_mean,
                         const float* __restrict__ W_disp,
                         const float* __restrict__ b_disp,
                         const float* __restrict__ W_pi,
                         const float* __restrict__ b_pi,
                         float* __restrict__ out,
                         int n_edges)
{
    const int tid   = blockIdx.x * BLOCK + threadIdx.x;
    const int e     = tid >> 3;        // edge index
    const int lane8 = tid & 7;         // 0..7 within the edge group
    if (e >= n_edges) return;

    const int u = edge_u[e];
    const int v = edge_v[e];

    // Each thread reads 8 contiguous floats (2 x float4) from each row.
    const float4* cp = reinterpret_cast<const float4*>(c_feat + (size_t)u * 64) + lane8 * 2;
    const float4* gp = reinterpret_cast<const float4*>(g_feat + (size_t)v * 64) + lane8 * 2;
    const float4 c0 = cp[0], c1 = cp[1];
    const float4 g0 = gp[0], g1 = gp[1];

    // Weights (uniform per lane position across all edges -> L1 broadcast hits)
    const float4* wm = reinterpret_cast<const float4*>(W_mean) + lane8 * 2;
    const float4* wd = reinterpret_cast<const float4*>(W_disp) + lane8 * 2;
    const float4* wp = reinterpret_cast<const float4*>(W_pi)   + lane8 * 2;
    const float4 wm0 = __ldg(wm), wm1 = __ldg(wm + 1);
    const float4 wd0 = __ldg(wd), wd1 = __ldg(wd + 1);
    const float4 wp0 = __ldg(wp), wp1 = __ldg(wp + 1);

    // h = c * g elementwise, then partial dots
    float h[8];
    h[0] = c0.x * g0.x; h[1] = c0.y * g0.y; h[2] = c0.z * g0.z; h[3] = c0.w * g0.w;
    h[4] = c1.x * g1.x; h[5] = c1.y * g1.y; h[6] = c1.z * g1.z; h[7] = c1.w * g1.w;

    float sm = h[0]*wm0.x + h[1]*wm0.y + h[2]*wm0.z + h[3]*wm0.w
             + h[4]*wm1.x + h[5]*wm1.y + h[6]*wm1.z + h[7]*wm1.w;
    float sd = h[0]*wd0.x + h[1]*wd0.y + h[2]*wd0.z + h[3]*wd0.w
             + h[4]*wd1.x + h[5]*wd1.y + h[6]*wd1.z + h[7]*wd1.w;
    float sp = h[0]*wp0.x + h[1]*wp0.y + h[2]*wp0.z + h[3]*wp0.w
             + h[4]*wp1.x + h[5]*wp1.y + h[6]*wp1.z + h[7]*wp1.w;

    // Reduce across the 8-lane group (group is aligned within the warp)
    #pragma unroll
    for (int off = 4; off > 0; off >>= 1) {
        sm += __shfl_xor_sync(0xffffffffu, sm, off);
        sd += __shfl_xor_sync(0xffffffffu, sd, off);
        sp += __shfl_xor_sync(0xffffffffu, sp, off);
    }

    if (lane8 == 0) {
        const float gs = gs_factor[v];
        const float cs = cs_factor[u];

        const float mu_   = sigmoidf_(sm + b_mean[0]);
        const float disp_ = sd + b_disp[0];
        const float pi    = sigmoidf_(sp + b_pi[0]);

        // softplus(x) = max(x,0) + log1p(exp(-|x|))  (numerically stable)
        const float x  = gs * disp_;
        const float sx = fmaxf(x, 0.0f) + log1pf(expf(-fabsf(x)));
        const float disp = fminf(fmaxf(sx, 1e-4f), 1e4f);

        const float mu = cs * fminf(fmaxf(expf(gs * mu_) - 1.0f, 1e-5f), 1e6f);

        out[e]                       = mu;
        out[(size_t)n_edges + e]     = disp;
        out[(size_t)2 * n_edges + e] = pi;
    }
}

extern "C" void kernel_launch(void* const* d_in, const int* in_sizes, int n_in,
                              void* d_out, int out_size) {
    const float* c_feat    = (const float*)d_in[0];
    const float* g_feat    = (const float*)d_in[1];
    const float* cs_factor = (const float*)d_in[2];
    const float* gs_factor = (const float*)d_in[3];
    const int*   edge_u    = (const int*)d_in[4];
    const int*   edge_v    = (const int*)d_in[5];
    const float* W_mean    = (const float*)d_in[6];
    const float* b_mean    = (const float*)d_in[7];
    const float* W_disp    = (const float*)d_in[8];
    const float* b_disp    = (const float*)d_in[9];
    const float* W_pi      = (const float*)d_in[10];
    const float* b_pi      = (const float*)d_in[11];

    const int n_edges = in_sizes[4];
    float* out = (float*)d_out;

    const long long total_threads = (long long)n_edges * THREADS_PER_EDGE;
    const int blocks = (int)((total_threads + BLOCK - 1) / BLOCK);

    zinb_decoder_kernel<<<blocks, BLOCK>>>(
        c_feat, g_feat, cs_factor, gs_factor, edge_u, edge_v,
        W_mean, b_mean, W_disp, b_disp, W_pi, b_pi,
        out, n_edges);
}

// round 2
// speedup vs baseline: 1.3653x; 1.3653x over previous
#include <cuda_runtime.h>
#include <cuda_bf16.h>

// ZINB decoder over 3M edges — persistent grid-stride version.
// 8 threads per edge; each thread owns 8 of the 64 feature dims and keeps
// its weight slice (3 x 8 floats) + biases in REGISTERS for its lifetime,
// eliminating the per-edge weight reload that dominated L1tex wavefronts.

#define THREADS_PER_EDGE 8
#define BLOCK 256
#define GROUPS_PER_BLOCK (BLOCK / THREADS_PER_EDGE)

__device__ __forceinline__ float sigmoidf_(float x) {
    return 1.0f / (1.0f + expf(-x));
}

__global__ __launch_bounds__(BLOCK)
void zinb_decoder_kernel(const float* __restrict__ c_feat,
                         const float* __restrict__ g_feat,
                         const float* __restrict__ cs_factor,
                         const float* __restrict__ gs_factor,
                         const int*   __restrict__ edge_u,
                         const int*   __restrict__ edge_v,
                         const float* __restrict__ W_mean,
                         const float* __restrict__ b_mean,
                         const float* __restrict__ W_disp,
                         const float* __restrict__ b_disp,
                         const float* __restrict__ W_pi,
                         const float* __restrict__ b_pi,
                         float* __restrict__ out,
                         int n_edges)
{
    const int lane8 = threadIdx.x & 7;   // 0..7 within the edge group

    // ---- hoisted: weight slice + biases, loaded ONCE per thread ----
    const float4* wm = reinterpret_cast<const float4*>(W_mean) + lane8 * 2;
    const float4* wd = reinterpret_cast<const float4*>(W_disp) + lane8 * 2;
    const float4* wp = reinterpret_cast<const float4*>(W_pi)   + lane8 * 2;
    const float4 wm0 = __ldg(wm), wm1 = __ldg(wm + 1);
    const float4 wd0 = __ldg(wd), wd1 = __ldg(wd + 1);
    const float4 wp0 = __ldg(wp), wp1 = __ldg(wp + 1);
    const float bm = __ldg(b_mean), bd = __ldg(b_disp), bp = __ldg(b_pi);

    const int group0 = blockIdx.x * GROUPS_PER_BLOCK + (threadIdx.x >> 3);
    const int stride = gridDim.x * GROUPS_PER_BLOCK;

    for (int e = group0; e < n_edges; e += stride) {
        const int u = edge_u[e];
        const int v = edge_v[e];

        const float4* cp = reinterpret_cast<const float4*>(c_feat + (size_t)u * 64) + lane8 * 2;
        const float4* gp = reinterpret_cast<const float4*>(g_feat + (size_t)v * 64) + lane8 * 2;
        const float4 c0 = cp[0], c1 = cp[1];
        const float4 g0 = gp[0], g1 = gp[1];

        float h0 = c0.x * g0.x, h1 = c0.y * g0.y, h2 = c0.z * g0.z, h3 = c0.w * g0.w;
        float h4 = c1.x * g1.x, h5 = c1.y * g1.y, h6 = c1.z * g1.z, h7 = c1.w * g1.w;

        float sm = h0*wm0.x + h1*wm0.y + h2*wm0.z + h3*wm0.w
                 + h4*wm1.x + h5*wm1.y + h6*wm1.z + h7*wm1.w;
        float sd = h0*wd0.x + h1*wd0.y + h2*wd0.z + h3*wd0.w
                 + h4*wd1.x + h5*wd1.y + h6*wd1.z + h7*wd1.w;
        float sp = h0*wp0.x + h1*wp0.y + h2*wp0.z + h3*wp0.w
                 + h4*wp1.x + h5*wp1.y + h6*wp1.z + h7*wp1.w;

        #pragma unroll
        for (int off = 4; off > 0; off >>= 1) {
            sm += __shfl_xor_sync(0xffffffffu, sm, off);
            sd += __shfl_xor_sync(0xffffffffu, sd, off);
            sp += __shfl_xor_sync(0xffffffffu, sp, off);
        }

        if (lane8 == 0) {
            const float gs = gs_factor[v];
            const float cs = cs_factor[u];

            const float mu_   = sigmoidf_(sm + bm);
            const float disp_ = sd + bd;
            const float pi    = sigmoidf_(sp + bp);

            // stable softplus
            const float x  = gs * disp_;
            const float sx = fmaxf(x, 0.0f) + log1pf(expf(-fabsf(x)));
            const float disp = fminf(fmaxf(sx, 1e-4f), 1e4f);

            const float mu = cs * fminf(fmaxf(expf(gs * mu_) - 1.0f, 1e-5f), 1e6f);

            out[e]                       = mu;
            out[(size_t)n_edges + e]     = disp;
            out[(size_t)2 * n_edges + e] = pi;
        }
    }
}

extern "C" void kernel_launch(void* const* d_in, const int* in_sizes, int n_in,
                              void* d_out, int out_size) {
    const float* c_feat    = (const float*)d_in[0];
    const float* g_feat    = (const float*)d_in[1];
    const float* cs_factor = (const float*)d_in[2];
    const float* gs_factor = (const float*)d_in[3];
    const int*   edge_u    = (const int*)d_in[4];
    const int*   edge_v    = (const int*)d_in[5];
    const float* W_mean    = (const float*)d_in[6];
    const float* b_mean    = (const float*)d_in[7];
    const float* W_disp    = (const float*)d_in[8];
    const float* b_disp    = (const float*)d_in[9];
    const float* W_pi      = (const float*)d_in[10];
    const float* b_pi      = (const float*)d_in[11];

    const int n_edges = in_sizes[4];
    float* out = (float*)d_out;

    // Persistent-ish grid: enough blocks to fill the chip several times over,
    // few enough that the per-thread weight-register hoist is amortized ~80x.
    const int blocks = 1184;  // 148 SMs * 8

    zinb_decoder_kernel<<<blocks, BLOCK>>>(
        c_feat, g_feat, cs_factor, gs_factor, edge_u, edge_v,
        W_mean, b_mean, W_disp, b_disp, W_pi, b_pi,
        out, n_edges);
}

// round 3
// speedup vs baseline: 1.6879x; 1.2363x over previous
#include <cuda_runtime.h>
#include <cuda_bf16.h>

// ZINB decoder over 3M edges — persistent, 2-edges-per-iteration, parallel epilogue.
// 8 threads per edge group; each group processes edges e and e+stride per loop
// iteration (8 outstanding LDG.128 gathers per thread). After butterfly
// reduction, the warp's 8 edge-sums are shuffled to lanes 0-7 which run the
// activation epilogue for 8 edges concurrently (identical code, no divergence).

#define BLOCK 256
#define GROUPS_PER_BLOCK (BLOCK / 8)

__global__ __launch_bounds__(BLOCK)
void zinb_decoder_kernel(const float* __restrict__ c_feat,
                         const float* __restrict__ g_feat,
                         const float* __restrict__ cs_factor,
                         const float* __restrict__ gs_factor,
                         const int*   __restrict__ edge_u,
                         const int*   __restrict__ edge_v,
                         const float* __restrict__ W_mean,
                         const float* __restrict__ b_mean,
                         const float* __restrict__ W_disp,
                         const float* __restrict__ b_disp,
                         const float* __restrict__ W_pi,
                         const float* __restrict__ b_pi,
                         float* __restrict__ out,
                         int n_edges)
{
    const unsigned FULL = 0xffffffffu;
    const int warpLane  = threadIdx.x & 31;
    const int grpInWarp = warpLane >> 3;    // 0..3
    const int lane8     = warpLane & 7;     // 0..7 within group

    // ---- weights + biases hoisted to registers (once per thread) ----
    const float4* wm = reinterpret_cast<const float4*>(W_mean) + lane8 * 2;
    const float4* wd = reinterpret_cast<const float4*>(W_disp) + lane8 * 2;
    const float4* wp = reinterpret_cast<const float4*>(W_pi)   + lane8 * 2;
    const float4 wm0 = __ldg(wm), wm1 = __ldg(wm + 1);
    const float4 wd0 = __ldg(wd), wd1 = __ldg(wd + 1);
    const float4 wp0 = __ldg(wp), wp1 = __ldg(wp + 1);
    const float bm = __ldg(b_mean), bd = __ldg(b_disp), bp = __ldg(b_pi);

    const int warpId = (blockIdx.x * BLOCK + threadIdx.x) >> 5;
    const int stride = gridDim.x * GROUPS_PER_BLOCK;   // total groups

    // ebase is warp-uniform; the warp's 4 groups own edges ebase..ebase+3 (set a)
    // and ebase+stride..ebase+stride+3 (set b) each iteration.
    for (int ebase = warpId * 4; ebase < n_edges; ebase += 2 * stride) {
        const int e_a = ebase + grpInWarp;
        const int e_b = e_a + stride;
        const bool va = e_a < n_edges;
        const bool vb = e_b < n_edges;

        const int u_a = va ? edge_u[e_a] : 0;
        const int v_a = va ? edge_v[e_a] : 0;
        const int u_b = vb ? edge_u[e_b] : 0;
        const int v_b = vb ? edge_v[e_b] : 0;

        // ---- issue all gathers up front (8 x LDG.128 + 4 scalars) ----
        const float4* cpa = reinterpret_cast<const float4*>(c_feat + (size_t)u_a * 64) + lane8 * 2;
        const float4* gpa = reinterpret_cast<const float4*>(g_feat + (size_t)v_a * 64) + lane8 * 2;
        const float4* cpb = reinterpret_cast<const float4*>(c_feat + (size_t)u_b * 64) + lane8 * 2;
        const float4* gpb = reinterpret_cast<const float4*>(g_feat + (size_t)v_b * 64) + lane8 * 2;
        const float4 ca0 = cpa[0], ca1 = cpa[1];
        const float4 ga0 = gpa[0], ga1 = gpa[1];
        const float4 cb0 = cpb[0], cb1 = cpb[1];
        const float4 gb0 = gpb[0], gb1 = gpb[1];
        const float gs_a = gs_factor[v_a];
        const float cs_a = cs_factor[u_a];
        const float gs_b = gs_factor[v_b];
        const float cs_b = cs_factor[u_b];

        // ---- edge a partial dots ----
        float h0 = ca0.x*ga0.x, h1 = ca0.y*ga0.y, h2 = ca0.z*ga0.z, h3 = ca0.w*ga0.w;
        float h4 = ca1.x*ga1.x, h5 = ca1.y*ga1.y, h6 = ca1.z*ga1.z, h7 = ca1.w*ga1.w;
        float sm_a = h0*wm0.x + h1*wm0.y + h2*wm0.z + h3*wm0.w
                   + h4*wm1.x + h5*wm1.y + h6*wm1.z + h7*wm1.w;
        float sd_a = h0*wd0.x + h1*wd0.y + h2*wd0.z + h3*wd0.w
                   + h4*wd1.x + h5*wd1.y + h6*wd1.z + h7*wd1.w;
        float sp_a = h0*wp0.x + h1*wp0.y + h2*wp0.z + h3*wp0.w
                   + h4*wp1.x + h5*wp1.y + h6*wp1.z + h7*wp1.w;

        // ---- edge b partial dots ----
        h0 = cb0.x*gb0.x; h1 = cb0.y*gb0.y; h2 = cb0.z*gb0.z; h3 = cb0.w*gb0.w;
        h4 = cb1.x*gb1.x; h5 = cb1.y*gb1.y; h6 = cb1.z*gb1.z; h7 = cb1.w*gb1.w;
        float sm_b = h0*wm0.x + h1*wm0.y + h2*wm0.z + h3*wm0.w
                   + h4*wm1.x + h5*wm1.y + h6*wm1.z + h7*wm1.w;
        float sd_b = h0*wd0.x + h1*wd0.y + h2*wd0.z + h3*wd0.w
                   + h4*wd1.x + h5*wd1.y + h6*wd1.z + h7*wd1.w;
        float sp_b = h0*wp0.x + h1*wp0.y + h2*wp0.z + h3*wp0.w
                   + h4*wp1.x + h5*wp1.y + h6*wp1.z + h7*wp1.w;

        // ---- butterfly reduce within each 8-lane group (6 independent chains) ----
        #pragma unroll
        for (int off = 4; off > 0; off >>= 1) {
            sm_a += __shfl_xor_sync(FULL, sm_a, off);
            sd_a += __shfl_xor_sync(FULL, sd_a, off);
            sp_a += __shfl_xor_sync(FULL, sp_a, off);
            sm_b += __shfl_xor_sync(FULL, sm_b, off);
            sd_b += __shfl_xor_sync(FULL, sd_b, off);
            sp_b += __shfl_xor_sync(FULL, sp_b, off);
        }

        // ---- gather the warp's 8 edges to lanes 0-7 for a parallel epilogue ----
        const int srcLane = (warpLane & 3) << 3;   // lane8==0 of group (warpLane&3)
        const float SMa = __shfl_sync(FULL, sm_a, srcLane);
        const float SDa = __shfl_sync(FULL, sd_a, srcLane);
        const float SPa = __shfl_sync(FULL, sp_a, srcLane);
        const float GSa = __shfl_sync(FULL, gs_a, srcLane);
        const float CSa = __shfl_sync(FULL, cs_a, srcLane);
        const float SMb = __shfl_sync(FULL, sm_b, srcLane);
        const float SDb = __shfl_sync(FULL, sd_b, srcLane);
        const float SPb = __shfl_sync(FULL, sp_b, srcLane);
        const float GSb = __shfl_sync(FULL, gs_b, srcLane);
        const float CSb = __shfl_sync(FULL, cs_b, srcLane);

        const bool second = (warpLane & 4) != 0;   // lanes 4-7 take set b
        const float SM = second ? SMb : SMa;
        const float SD = second ? SDb : SDa;
        const float SP = second ? SPb : SPa;
        const float GS = second ? GSb : GSa;
        const float CS = second ? CSb : CSa;
        const int   eo = ebase + (warpLane & 3) + (second ? stride : 0);

        if (warpLane < 8 && eo < n_edges) {
            const float mu_ = 1.0f / (1.0f + expf(-(SM + bm)));
            const float pi  = 1.0f / (1.0f + expf(-(SP + bp)));

            const float x  = GS * (SD + bd);
            const float sx = fmaxf(x, 0.0f) + log1pf(expf(-fabsf(x)));
            const float disp = fminf(fmaxf(sx, 1e-4f), 1e4f);

            const float mu = CS * fminf(fmaxf(expf(GS * mu_) - 1.0f, 1e-5f), 1e6f);

            out[eo]                       = mu;
            out[(size_t)n_edges + eo]     = disp;
            out[(size_t)2 * n_edges + eo] = pi;
        }
    }
}

extern "C" void kernel_launch(void* const* d_in, const int* in_sizes, int n_in,
                              void* d_out, int out_size) {
    const float* c_feat    = (const float*)d_in[0];
    const float* g_feat    = (const float*)d_in[1];
    const float* cs_factor = (const float*)d_in[2];
    const float* gs_factor = (const float*)d_in[3];
    const int*   edge_u    = (const int*)d_in[4];
    const int*   edge_v    = (const int*)d_in[5];
    const float* W_mean    = (const float*)d_in[6];
    const float* b_mean    = (const float*)d_in[7];
    const float* W_disp    = (const float*)d_in[8];
    const float* b_disp    = (const float*)d_in[9];
    const float* W_pi      = (const float*)d_in[10];
    const float* b_pi      = (const float*)d_in[11];

    const int n_edges = in_sizes[4];
    float* out = (float*)d_out;

    const int blocks = 1184;  // 148 SMs * 8; grid-stride absorbs imbalance

    zinb_decoder_kernel<<<blocks, BLOCK>>>(
        c_feat, g_feat, cs_factor, gs_factor, edge_u, edge_v,
        W_mean, b_mean, W_disp, b_disp, W_pi, b_pi,
        out, n_edges);
}

// round 4
// speedup vs baseline: 1.9059x; 1.1292x over previous
#include <cuda_runtime.h>
#include <cuda_bf16.h>

// ZINB decoder over 3M edges — persistent, 2 edges/group/iter, line-aligned gathers.
// Thread lane8 loads float4 index lane8 and lane8+8 of each 64-float row, so each
// warp-wide gather instruction touches exactly one 128B line per 8-lane group
// (4 lines/warp, 100% line utilization) instead of the strided 2-lines-at-50%.
// gs/cs are gathered directly by the 8 epilogue lanes, issued at iteration start.

#define BLOCK 256
#define GROUPS_PER_BLOCK (BLOCK / 8)

__global__ __launch_bounds__(BLOCK)
void zinb_decoder_kernel(const float* __restrict__ c_feat,
                         const float* __restrict__ g_feat,
                         const float* __restrict__ cs_factor,
                         const float* __restrict__ gs_factor,
                         const int*   __restrict__ edge_u,
                         const int*   __restrict__ edge_v,
                         const float* __restrict__ W_mean,
                         const float* __restrict__ b_mean,
                         const float* __restrict__ W_disp,
                         const float* __restrict__ b_disp,
                         const float* __restrict__ W_pi,
                         const float* __restrict__ b_pi,
                         float* __restrict__ out,
                         int n_edges)
{
    const unsigned FULL = 0xffffffffu;
    const int warpLane  = threadIdx.x & 31;
    const int grpInWarp = warpLane >> 3;    // 0..3
    const int lane8     = warpLane & 7;     // 0..7 within group

    // ---- weights + biases hoisted to registers (line-aligned mapping) ----
    const float4* wmv = reinterpret_cast<const float4*>(W_mean);
    const float4* wdv = reinterpret_cast<const float4*>(W_disp);
    const float4* wpv = reinterpret_cast<const float4*>(W_pi);
    const float4 wm0 = __ldg(wmv + lane8), wm1 = __ldg(wmv + lane8 + 8);
    const float4 wd0 = __ldg(wdv + lane8), wd1 = __ldg(wdv + lane8 + 8);
    const float4 wp0 = __ldg(wpv + lane8), wp1 = __ldg(wpv + lane8 + 8);
    const float bm = __ldg(b_mean), bd = __ldg(b_disp), bp = __ldg(b_pi);

    const int warpId = (blockIdx.x * BLOCK + threadIdx.x) >> 5;
    const int stride = gridDim.x * GROUPS_PER_BLOCK;   // total groups

    const bool second  = (warpLane & 4) != 0;          // epilogue lanes 4-7 take set b
    const int  eoLocal = (warpLane & 3);

    for (int ebase = warpId * 4; ebase < n_edges; ebase += 2 * stride) {
        const int e_a = ebase + grpInWarp;
        const int e_b = e_a + stride;
        const bool va = e_a < n_edges;
        const bool vb = e_b < n_edges;

        const int u_a = va ? edge_u[e_a] : 0;
        const int v_a = va ? edge_v[e_a] : 0;
        const int u_b = vb ? edge_u[e_b] : 0;
        const int v_b = vb ? edge_v[e_b] : 0;

        // ---- epilogue-lane scalar gathers, issued early (pattern repeats every
        //      8 lanes -> lanes 8-31 duplicate addresses, no extra cache lines) ----
        const int eo  = ebase + eoLocal + (second ? stride : 0);
        const int eoc = eo < n_edges ? eo : 0;
        const float GS = gs_factor[edge_v[eoc]];
        const float CS = cs_factor[edge_u[eoc]];

        // ---- feature gathers: one 128B line per group per instruction ----
        const float4* cpa = reinterpret_cast<const float4*>(c_feat + (size_t)u_a * 64);
        const float4* gpa = reinterpret_cast<const float4*>(g_feat + (size_t)v_a * 64);
        const float4* cpb = reinterpret_cast<const float4*>(c_feat + (size_t)u_b * 64);
        const float4* gpb = reinterpret_cast<const float4*>(g_feat + (size_t)v_b * 64);
        const float4 ca0 = cpa[lane8], ca1 = cpa[lane8 + 8];
        const float4 ga0 = gpa[lane8], ga1 = gpa[lane8 + 8];
        const float4 cb0 = cpb[lane8], cb1 = cpb[lane8 + 8];
        const float4 gb0 = gpb[lane8], gb1 = gpb[lane8 + 8];

        // ---- edge a partial dots ----
        float h0 = ca0.x*ga0.x, h1 = ca0.y*ga0.y, h2 = ca0.z*ga0.z, h3 = ca0.w*ga0.w;
        float h4 = ca1.x*ga1.x, h5 = ca1.y*ga1.y, h6 = ca1.z*ga1.z, h7 = ca1.w*ga1.w;
        float sm_a = h0*wm0.x + h1*wm0.y + h2*wm0.z + h3*wm0.w
                   + h4*wm1.x + h5*wm1.y + h6*wm1.z + h7*wm1.w;
        float sd_a = h0*wd0.x + h1*wd0.y + h2*wd0.z + h3*wd0.w
                   + h4*wd1.x + h5*wd1.y + h6*wd1.z + h7*wd1.w;
        float sp_a = h0*wp0.x + h1*wp0.y + h2*wp0.z + h3*wp0.w
                   + h4*wp1.x + h5*wp1.y + h6*wp1.z + h7*wp1.w;

        // ---- edge b partial dots ----
        h0 = cb0.x*gb0.x; h1 = cb0.y*gb0.y; h2 = cb0.z*gb0.z; h3 = cb0.w*gb0.w;
        h4 = cb1.x*gb1.x; h5 = cb1.y*gb1.y; h6 = cb1.z*gb1.z; h7 = cb1.w*gb1.w;
        float sm_b = h0*wm0.x + h1*wm0.y + h2*wm0.z + h3*wm0.w
                   + h4*wm1.x + h5*wm1.y + h6*wm1.z + h7*wm1.w;
        float sd_b = h0*wd0.x + h1*wd0.y + h2*wd0.z + h3*wd0.w
                   + h4*wd1.x + h5*wd1.y + h6*wd1.z + h7*wd1.w;
        float sp_b = h0*wp0.x + h1*wp0.y + h2*wp0.z + h3*wp0.w
                   + h4*wp1.x + h5*wp1.y + h6*wp1.z + h7*wp1.w;

        // ---- butterfly reduce within each 8-lane group ----
        #pragma unroll
        for (int off = 4; off > 0; off >>= 1) {
            sm_a += __shfl_xor_sync(FULL, sm_a, off);
            sd_a += __shfl_xor_sync(FULL, sd_a, off);
            sp_a += __shfl_xor_sync(FULL, sp_a, off);
            sm_b += __shfl_xor_sync(FULL, sm_b, off);
            sd_b += __shfl_xor_sync(FULL, sd_b, off);
            sp_b += __shfl_xor_sync(FULL, sp_b, off);
        }

        // ---- distribute the warp's 8 edges to lanes 0-7 ----
        const int srcLane = eoLocal << 3;   // lane8==0 of group (warpLane&3)
        const float SMa = __shfl_sync(FULL, sm_a, srcLane);
        const float SDa = __shfl_sync(FULL, sd_a, srcLane);
        const float SPa = __shfl_sync(FULL, sp_a, srcLane);
        const float SMb = __shfl_sync(FULL, sm_b, srcLane);
        const float SDb = __shfl_sync(FULL, sd_b, srcLane);
        const float SPb = __shfl_sync(FULL, sp_b, srcLane);

        const float SM = second ? SMb : SMa;
        const float SD = second ? SDb : SDa;
        const float SP = second ? SPb : SPa;

        if (warpLane < 8 && eo < n_edges) {
            const float mu_ = 1.0f / (1.0f + expf(-(SM + bm)));
            const float pi  = 1.0f / (1.0f + expf(-(SP + bp)));

            const float x  = GS * (SD + bd);
            const float sx = fmaxf(x, 0.0f) + log1pf(expf(-fabsf(x)));
            const float disp = fminf(fmaxf(sx, 1e-4f), 1e4f);

            const float mu = CS * fminf(fmaxf(expf(GS * mu_) - 1.0f, 1e-5f), 1e6f);

            out[eo]                       = mu;
            out[(size_t)n_edges + eo]     = disp;
            out[(size_t)2 * n_edges + eo] = pi;
        }
    }
}

extern "C" void kernel_launch(void* const* d_in, const int* in_sizes, int n_in,
                              void* d_out, int out_size) {
    const float* c_feat    = (const float*)d_in[0];
    const float* g_feat    = (const float*)d_in[1];
    const float* cs_factor = (const float*)d_in[2];
    const float* gs_factor = (const float*)d_in[3];
    const int*   edge_u    = (const int*)d_in[4];
    const int*   edge_v    = (const int*)d_in[5];
    const float* W_mean    = (const float*)d_in[6];
    const float* b_mean    = (const float*)d_in[7];
    const float* W_disp    = (const float*)d_in[8];
    const float* b_disp    = (const float*)d_in[9];
    const float* W_pi      = (const float*)d_in[10];
    const float* b_pi      = (const float*)d_in[11];

    const int n_edges = in_sizes[4];
    float* out = (float*)d_out;

    const int blocks = 1184;  // 148 SMs * 8; grid-stride absorbs imbalance

    zinb_decoder_kernel<<<blocks, BLOCK>>>(
        c_feat, g_feat, cs_factor, gs_factor, edge_u, edge_v,
        W_mean, b_mean, W_disp, b_disp, W_pi, b_pi,
        out, n_edges);
}